// round 14
// baseline (speedup 1.0000x reference)
#include <cuda_runtime.h>
#include <cuda_fp16.h>
#include <cstdint>

// ---------------- problem constants ----------------
#define Bz   8
#define Dd   4096
#define TD   512
#define WD   512
#define SLOPE 0.01f

// ---------------- scratch (static device globals) ----------------
__device__ float g_hs [Bz * 65 * Dd];
__device__ float g_q  [Bz * 65 * Dd];
__device__ float g_k  [Bz * 65 * Dd];
__device__ float g_v  [Bz * 65 * Dd];
__device__ float g_q2 [Bz * 64 * Dd];
__device__ float g_v2 [Bz * 64 * Dd];
__device__ float g_sc1[Bz * 65 * 65];
__device__ float g_sc2[Bz * 65 * 65];
__device__ float g_a  [Bz * 64 * Dd];
__device__ float g_h  [Bz * 64 * Dd];

// ================= fp16 mma.sync GEMM + ldmatrix, BK=128 =================
// C[z][M, 4096 (stride cstride)] = A[M,K] @ W[z][K,4096] + bias[z] (+leaky)
// CTA 128x128, BK=128 (two sequential 64-k half-loads sharing one register
// set), 512 thr, warp grid 4m x 4n, warp tile 32x32.

#define KPA 136
#define KPB 136
#define A_HALVES (128 * KPA)
#define B_HALVES (128 * KPB)
#define STAGE_HALVES (A_HALVES + B_HALVES)
#define GEMM_SMEM (2 * STAGE_HALVES * 2)  // 139264 bytes

__device__ __forceinline__ uint32_t smem_u32(const void* p) {
    uint32_t a;
    asm("{ .reg .u64 t; cvta.to.shared.u64 t, %1; cvt.u32.u64 %0, t; }" : "=r"(a) : "l"(p));
    return a;
}
__device__ __forceinline__ void ldsm4(uint32_t& r0, uint32_t& r1, uint32_t& r2,
                                      uint32_t& r3, uint32_t addr) {
    asm volatile("ldmatrix.sync.aligned.m8n8.x4.shared.b16 {%0,%1,%2,%3}, [%4];"
                 : "=r"(r0), "=r"(r1), "=r"(r2), "=r"(r3) : "r"(addr));
}

__global__ __launch_bounds__(512, 1)
void mma_gemm(const float* __restrict__ A,
              const float* __restrict__ W0, const float* __restrict__ W1,
              const float* __restrict__ W2,
              const float* __restrict__ b0, const float* __restrict__ b1,
              const float* __restrict__ b2,
              float* __restrict__ C0, float* __restrict__ C1, float* __restrict__ C2,
              int M, int K, int act, int cstride)
{
    const float* W    = (blockIdx.z == 0) ? W0 : (blockIdx.z == 1) ? W1 : W2;
    const float* bias = (blockIdx.z == 0) ? b0 : (blockIdx.z == 1) ? b1 : b2;
    float*       C    = (blockIdx.z == 0) ? C0 : (blockIdx.z == 1) ? C1 : C2;

    extern __shared__ __align__(16) __half smh[];
    const uint32_t smb = smem_u32(smh);
    const int tid  = threadIdx.x;
    const int wid  = tid >> 5;
    const int lane = tid & 31;
    const int bn = blockIdx.x << 7;
    const int bm = blockIdx.y << 7;
    const int wm = (wid >> 2) << 5;
    const int wn = (wid & 3) << 5;
    const int r  = lane >> 2;
    const int c  = lane & 3;

    const int mrem  = M - bm - wm;
    const int mtmax = (mrem >= 32) ? 2 : ((mrem <= 0) ? 0 : 1);

    const int b_n  = tid & 127, b_kq = tid >> 7;

    const int t8   = lane >> 3;
    const int row8 = lane & 7;
    const uint32_t a_lm = (uint32_t)((wm + (t8 & 1) * 8 + row8) * KPA * 2 + (t8 >> 1) * 16);
    const uint32_t b_lm = (uint32_t)((wn + (t8 & 1) * 8 + row8) * KPB * 2 + (t8 >> 1) * 16)
                        + A_HALVES * 2;

    float acc[2][4][4];
    #pragma unroll
    for (int i = 0; i < 2; i++)
        #pragma unroll
        for (int j = 0; j < 4; j++)
            #pragma unroll
            for (int t = 0; t < 4; t++) acc[i][j][t] = 0.f;

    const int nkb = K >> 7;   // BK = 128
    float4 ar[4];             // A: 128 rows x 16 f4 per 64-k half
    float  br[4][4];          // B: 64 k-rows x 128 n per 64-k half

    // half ∈ {0,1}: k-columns [kb*128 + half*64, +64)
    auto ldg_half = [&](int kb, int half) {
        const int kcol = (kb << 7) + (half << 6);
        #pragma unroll
        for (int i = 0; i < 4; i++) {
            int idx = tid + i * 512;
            int m   = idx >> 4;        // 0..127
            int f4  = idx & 15;        // 0..15 -> 64 floats
            int gm  = bm + m;
            if (gm >= M) gm = M - 1;
            ar[i] = (bm + m < M)
                  ? *(const float4*)(A + (size_t)gm * K + kcol + f4 * 4)
                  : make_float4(0.f, 0.f, 0.f, 0.f);
        }
        #pragma unroll
        for (int i = 0; i < 4; i++) {
            int k0 = (b_kq + i * 4) * 4;   // 0..60: 64 k-rows
            #pragma unroll
            for (int j = 0; j < 4; j++)
                br[i][j] = W[(size_t)(kcol + k0 + j) * 4096 + bn + b_n];
        }
    };

    auto sts_half = [&](int buf, int half) {
        __half* as_ = smh + buf * STAGE_HALVES + (half << 6);
        __half* bs_ = smh + buf * STAGE_HALVES + A_HALVES + (half << 6);
        #pragma unroll
        for (int i = 0; i < 4; i++) {
            int idx = tid + i * 512;
            int m   = idx >> 4;
            int f4  = idx & 15;
            uint2 u;
            *(__half2*)&u.x = __floats2half2_rn(ar[i].x, ar[i].y);
            *(__half2*)&u.y = __floats2half2_rn(ar[i].z, ar[i].w);
            *(uint2*)(as_ + m * KPA + f4 * 4) = u;
        }
        #pragma unroll
        for (int i = 0; i < 4; i++) {
            int k0 = (b_kq + i * 4) * 4;
            uint2 u;
            *(__half2*)&u.x = __floats2half2_rn(br[i][0], br[i][1]);
            *(__half2*)&u.y = __floats2half2_rn(br[i][2], br[i][3]);
            *(uint2*)(bs_ + b_n * KPB + k0) = u;
        }
    };

    ldg_half(0, 0);

    for (int kb = 0; kb < nkb; kb++) {
        sts_half(kb & 1, 0);
        ldg_half(kb, 1);
        sts_half(kb & 1, 1);
        __syncthreads();
        if (kb + 1 < nkb) ldg_half(kb + 1, 0);

        const uint32_t stage = smb + (uint32_t)(kb & 1) * STAGE_HALVES * 2;

        #pragma unroll
        for (int ks = 0; ks < 8; ks++) {
            const uint32_t ksoff = (uint32_t)ks * 32;   // 16 halves per step
            uint32_t af[2][4];
            #pragma unroll
            for (int mt = 0; mt < 2; mt++) {
                if (mt < mtmax)
                    ldsm4(af[mt][0], af[mt][1], af[mt][2], af[mt][3],
                          stage + a_lm + (uint32_t)(mt * 16 * KPA * 2) + ksoff);
            }
            uint32_t bf[4][2];
            #pragma unroll
            for (int p = 0; p < 2; p++) {
                ldsm4(bf[2 * p][0], bf[2 * p + 1][0], bf[2 * p][1], bf[2 * p + 1][1],
                      stage + b_lm + (uint32_t)(p * 16 * KPB * 2) + ksoff);
            }
            #pragma unroll
            for (int mt = 0; mt < 2; mt++) {
                if (mt < mtmax) {
                    #pragma unroll
                    for (int nt = 0; nt < 4; nt++) {
                        asm volatile(
                            "mma.sync.aligned.m16n8k16.row.col.f32.f16.f16.f32 "
                            "{%0,%1,%2,%3}, {%4,%5,%6,%7}, {%8,%9}, {%0,%1,%2,%3};"
                            : "+f"(acc[mt][nt][0]), "+f"(acc[mt][nt][1]),
                              "+f"(acc[mt][nt][2]), "+f"(acc[mt][nt][3])
                            : "r"(af[mt][0]), "r"(af[mt][1]),
                              "r"(af[mt][2]), "r"(af[mt][3]),
                              "r"(bf[nt][0]), "r"(bf[nt][1]));
                    }
                }
            }
        }
    }

    #pragma unroll
    for (int mt = 0; mt < 2; mt++) {
        if (mt >= mtmax) continue;
        int row0 = bm + wm + mt * 16 + r;
        int row1 = row0 + 8;
        #pragma unroll
        for (int nt = 0; nt < 4; nt++) {
            int col = bn + wn + nt * 8 + c * 2;
            float bb0 = bias[col], bb1 = bias[col + 1];
            if (row0 < M) {
                float v0 = acc[mt][nt][0] + bb0;
                float v1 = acc[mt][nt][1] + bb1;
                if (act) { v0 = v0 >= 0.f ? v0 : SLOPE * v0; v1 = v1 >= 0.f ? v1 : SLOPE * v1; }
                *(float2*)(C + (size_t)row0 * cstride + col) = make_float2(v0, v1);
            }
            if (row1 < M) {
                float v2 = acc[mt][nt][2] + bb0;
                float v3 = acc[mt][nt][3] + bb1;
                if (act) { v2 = v2 >= 0.f ? v2 : SLOPE * v2; v3 = v3 >= 0.f ? v3 : SLOPE * v3; }
                *(float2*)(C + (size_t)row1 * cstride + col) = make_float2(v2, v3);
            }
        }
    }
}

// ================= attention =================

__global__ void zero_sc_kernel(float* sc)
{
    int idx = blockIdx.x * blockDim.x + threadIdx.x;
    if (idx < Bz * 65 * 65) sc[idx] = 0.f;
}

#define SCW 81
#define SC_SMEM (2 * 128 * SCW * 4)

__global__ __launch_bounds__(256)
void attn_scores_part(const float* __restrict__ Q, const float* __restrict__ Km,
                      float* __restrict__ SC, int Sq, int Sk, int qbs, int kbs)
{
    extern __shared__ __align__(16) float sq[];
    float* sk = sq + 128 * SCW;
    __shared__ float kn[80];

    const int b  = blockIdx.y;
    const int ch = blockIdx.x;
    const int tid = threadIdx.x;
    const int ty = tid >> 4, tx = tid & 15;

    for (int e = tid; e < Sq * 128; e += 256) {
        int i  = e >> 7;
        int kk = e & 127;
        sq[kk * SCW + i] = Q[((size_t)b * qbs + i) * Dd + ch * 128 + kk];
    }
    for (int e = tid; e < Sk * 128; e += 256) {
        int j  = e >> 7;
        int kk = e & 127;
        sk[kk * SCW + j] = Km[((size_t)b * kbs + j) * Dd + ch * 128 + kk];
    }
    __syncthreads();

    if (tid < Sk) {
        float s = 0.f;
        #pragma unroll 8
        for (int kk = 0; kk < 128; kk++) {
            float v = sk[kk * SCW + tid];
            s += v * v;
        }
        kn[tid] = s;
    }
    __syncthreads();

    float acc[5][5];
    #pragma unroll
    for (int u = 0; u < 5; u++)
        #pragma unroll
        for (int v = 0; v < 5; v++) acc[u][v] = 0.f;

    #pragma unroll 4
    for (int kk = 0; kk < 128; kk++) {
        float a[5], bb[5];
        #pragma unroll
        for (int u = 0; u < 5; u++) a[u]  = sq[kk * SCW + ty * 5 + u];
        #pragma unroll
        for (int v = 0; v < 5; v++) bb[v] = sk[kk * SCW + tx * 5 + v];
        #pragma unroll
        for (int u = 0; u < 5; u++)
            #pragma unroll
            for (int v = 0; v < 5; v++) acc[u][v] += a[u] * bb[v];
    }

    #pragma unroll
    for (int u = 0; u < 5; u++) {
        int i = ty * 5 + u;
        if (i >= Sq) continue;
        #pragma unroll
        for (int v = 0; v < 5; v++) {
            int j = tx * 5 + v;
            if (j >= Sk) continue;
            atomicAdd(&SC[((size_t)b * 65 + i) * 65 + j], 2.f * acc[u][v] - kn[j]);
        }
    }
}

__global__ __launch_bounds__(32)
void softmax_kernel(float* __restrict__ SC, int Sk)
{
    int b = blockIdx.y, i = blockIdx.x;
    float* row = SC + ((size_t)b * 65 + i) * 65;
    int lane = threadIdx.x;

    float v0 = (lane      < Sk) ? row[lane]      : -1e30f;
    float v1 = (lane + 32 < Sk) ? row[lane + 32] : -1e30f;
    float v2 = (lane + 64 < Sk) ? row[lane + 64] : -1e30f;
    float mx = fmaxf(v0, fmaxf(v1, v2));
    #pragma unroll
    for (int o = 16; o; o >>= 1) mx = fmaxf(mx, __shfl_xor_sync(0xffffffff, mx, o));
    float e0 = (lane      < Sk) ? __expf(v0 - mx) : 0.f;
    float e1 = (lane + 32 < Sk) ? __expf(v1 - mx) : 0.f;
    float e2 = (lane + 64 < Sk) ? __expf(v2 - mx) : 0.f;
    float s = e0 + e1 + e2;
    #pragma unroll
    for (int o = 16; o; o >>= 1) s += __shfl_xor_sync(0xffffffff, s, o);
    float inv = 1.f / s;
    if (lane      < Sk) row[lane]      = e0 * inv;
    if (lane + 32 < Sk) row[lane + 32] = e1 * inv;
    if (lane + 64 < Sk) row[lane + 64] = e2 * inv;
}

#define AO_SMEM ((65 * 128 + 65 * 64) * 4)

__global__ __launch_bounds__(256)
void attn_out_chunk(const float* __restrict__ SC, const float* __restrict__ V,
                    float* __restrict__ Out, int Sq, int vbs)
{
    extern __shared__ __align__(16) float svs[];
    float* sw = svs + 65 * 128;

    const int b  = blockIdx.y;
    const int ch = blockIdx.x;
    const int tid = threadIdx.x;
    const int tx = tid & 31, ty = tid >> 5;

    for (int e = tid; e < Sq * 128; e += 256) {
        int i  = e >> 7;
        int kk = e & 127;
        svs[e] = V[((size_t)b * vbs + i) * Dd + ch * 128 + kk];
    }
    for (int e = tid; e < Sq * 64; e += 256) {
        int i = e >> 6;
        int j = e & 63;
        sw[e] = SC[((size_t)b * 65 + i) * 65 + j];
    }
    __syncthreads();

    float acc[8][4];
    #pragma unroll
    for (int u = 0; u < 8; u++)
        #pragma unroll
        for (int t = 0; t < 4; t++) acc[u][t] = 0.f;

    for (int i = 0; i < Sq; i++) {
        float4 v4 = *(const float4*)(svs + i * 128 + tx * 4);
        #pragma unroll
        for (int u = 0; u < 8; u++) {
            float w = sw[i * 64 + ty * 8 + u];
            acc[u][0] += w * v4.x;
            acc[u][1] += w * v4.y;
            acc[u][2] += w * v4.z;
            acc[u][3] += w * v4.w;
        }
    }

    #pragma unroll
    for (int u = 0; u < 8; u++) {
        int j = ty * 8 + u;
        *(float4*)(Out + ((size_t)b * 64 + j) * Dd + ch * 128 + tx * 4) =
            make_float4(acc[u][0], acc[u][1], acc[u][2], acc[u][3]);
    }
}

// ================= layout kernels =================
__global__ __launch_bounds__(256)
void patchify_kernel(const float* __restrict__ x, float* __restrict__ hs)
{
    __shared__ float tile[64][65];
    const int y = blockIdx.x;
    const int b = blockIdx.y;
    const int tid = threadIdx.x;
    const int jb = y >> 3, pr = y & 7;

    #pragma unroll
    for (int p = 0; p < 16; p++) {
        int cc = p * 4 + (tid >> 6);
        int xw = tid & 63;
        tile[cc][xw] = x[(((size_t)b * 64 + cc) * 64 + y) * 64 + xw];
    }
    __syncthreads();
    #pragma unroll
    for (int p = 0; p < 16; p++) {
        int xw = p * 4 + (tid >> 6);
        int cc = tid & 63;
        int ib = xw >> 3, pc = xw & 7;
        int n = ib * 8 + jb;
        int d = (pr * 8 + pc) * 64 + cc;
        hs[((size_t)b * 65 + n) * Dd + d] = tile[cc][xw];
    }
}

__global__ __launch_bounds__(256)
void depatchify_kernel(const float* __restrict__ h, float* __restrict__ out)
{
    __shared__ float tile[64][65];
    const int y = blockIdx.x;
    const int b = blockIdx.y;
    const int tid = threadIdx.x;
    const int jb = y >> 3, pr = y & 7;

    #pragma unroll
    for (int p = 0; p < 16; p++) {
        int xw = p * 4 + (tid >> 6);
        int cc = tid & 63;
        int ib = xw >> 3, pc = xw & 7;
        int n = ib * 8 + jb;
        int d = (pr * 8 + pc) * 64 + cc;
        tile[cc][xw] = h[((size_t)b * 64 + n) * Dd + d];
    }
    __syncthreads();
    #pragma unroll
    for (int p = 0; p < 16; p++) {
        int cc = p * 4 + (tid >> 6);
        int xw = tid & 63;
        out[(((size_t)b * 64 + cc) * 64 + y) * 64 + xw] = tile[cc][xw];
    }
}

// ================= host sequence =================
static void run_gemm3(const float* A,
                      const float* W0, const float* W1, const float* W2,
                      const float* b0, const float* b1, const float* b2,
                      float* C0, float* C1, float* C2,
                      int M, int K, int nz, int act, int cstride)
{
    dim3 grid(32, (M + 127) / 128, nz);
    mma_gemm<<<grid, 512, GEMM_SMEM>>>(A, W0, W1, W2, b0, b1, b2,
                                       C0, C1, C2, M, K, act, cstride);
}

extern "C" void kernel_launch(void* const* d_in, const int* in_sizes, int n_in,
                              void* d_out, int out_size)
{
    const float* x          = (const float*)d_in[0];
    const float* w          = (const float*)d_in[1];
    const float* t_local    = (const float*)d_in[2];
    const float* sa_style_w = (const float*)d_in[3];
    const float* sa_style_b = (const float*)d_in[4];
    const float* sa_kk = (const float*)d_in[5];
    const float* sa_kb = (const float*)d_in[6];
    const float* sa_qk = (const float*)d_in[7];
    const float* sa_qb = (const float*)d_in[8];
    const float* sa_vk = (const float*)d_in[9];
    const float* sa_vb = (const float*)d_in[10];
    const float* sa_ok = (const float*)d_in[11];
    const float* sa_ob = (const float*)d_in[12];
    const float* ca_kk = (const float*)d_in[13];
    const float* ca_kb = (const float*)d_in[14];
    const float* ca_qk = (const float*)d_in[15];
    const float* ca_qb = (const float*)d_in[16];
    const float* ca_vk = (const float*)d_in[17];
    const float* ca_vb = (const float*)d_in[18];
    const float* ca_ok = (const float*)d_in[19];
    const float* ca_ob = (const float*)d_in[20];
    float* out = (float*)d_out;

    float *hs, *q, *k, *v, *q2, *v2, *sc1, *sc2, *a, *h;
    cudaGetSymbolAddress((void**)&hs,  g_hs);
    cudaGetSymbolAddress((void**)&q,   g_q);
    cudaGetSymbolAddress((void**)&k,   g_k);
    cudaGetSymbolAddress((void**)&v,   g_v);
    cudaGetSymbolAddress((void**)&q2,  g_q2);
    cudaGetSymbolAddress((void**)&v2,  g_v2);
    cudaGetSymbolAddress((void**)&sc1, g_sc1);
    cudaGetSymbolAddress((void**)&sc2, g_sc2);
    cudaGetSymbolAddress((void**)&a,   g_a);
    cudaGetSymbolAddress((void**)&h,   g_h);

    cudaFuncSetAttribute(mma_gemm, cudaFuncAttributeMaxDynamicSharedMemorySize, GEMM_SMEM);
    cudaFuncSetAttribute(attn_scores_part, cudaFuncAttributeMaxDynamicSharedMemorySize, SC_SMEM);
    cudaFuncSetAttribute(attn_out_chunk, cudaFuncAttributeMaxDynamicSharedMemorySize, AO_SMEM);

    zero_sc_kernel<<<(Bz * 65 * 65 + 255) / 256, 256>>>(sc1);
    zero_sc_kernel<<<(Bz * 65 * 65 + 255) / 256, 256>>>(sc2);
    patchify_kernel<<<dim3(64, Bz), 256>>>(x, hs);
    run_gemm3(w, sa_style_w, sa_style_w, sa_style_w,
              sa_style_b, sa_style_b, sa_style_b,
              hs + 64 * Dd, hs + 64 * Dd, hs + 64 * Dd,
              Bz, WD, 1, 0, 65 * Dd);
    run_gemm3(t_local, ca_qk, ca_vk, ca_vk, ca_qb, ca_vb, ca_vb,
              q2, v2, v2, Bz * 64, TD, 2, 0, Dd);

    // SA q/k/v fused (M=520, K=4096, z=3)
    run_gemm3(hs, sa_qk, sa_kk, sa_vk, sa_qb, sa_kb, sa_vb,
              q, k, v, Bz * 65, Dd, 3, 0, Dd);

    // SA L2 attention
    attn_scores_part<<<dim3(32, Bz), 256, SC_SMEM>>>(q, k, sc1, 65, 65, 65, 65);
    softmax_kernel<<<dim3(65, Bz), 32>>>(sc1, 65);
    attn_out_chunk<<<dim3(32, Bz), 256, AO_SMEM>>>(sc1, v, a, 65, 65);

    // SA output projection + leaky relu
    run_gemm3(a, sa_ok, sa_ok, sa_ok, sa_ob, sa_ob, sa_ob,
              h, h, h, Bz * 64, Dd, 1, 1, Dd);

    // CA key projection
    run_gemm3(h, ca_kk, ca_kk, ca_kk, ca_kb, ca_kb, ca_kb,
              k, k, k, Bz * 64, Dd, 1, 0, Dd);

    // CA L2 attention
    attn_scores_part<<<dim3(32, Bz), 256, SC_SMEM>>>(q2, k, sc2, 64, 64, 64, 64);
    softmax_kernel<<<dim3(64, Bz), 32>>>(sc2, 64);
    attn_out_chunk<<<dim3(32, Bz), 256, AO_SMEM>>>(sc2, v2, a, 64, 64);

    // CA output projection + leaky relu
    run_gemm3(a, ca_ok, ca_ok, ca_ok, ca_ob, ca_ob, ca_ob,
              h, h, h, Bz * 64, Dd, 1, 1, Dd);

    depatchify_kernel<<<dim3(64, Bz), 256>>>(h, out);
}

// round 15
// speedup vs baseline: 1.1364x; 1.1364x over previous
#include <cuda_runtime.h>
#include <cuda_fp16.h>
#include <cstdint>

// ---------------- problem constants ----------------
#define Bz   8
#define Dd   4096
#define TD   512
#define WD   512
#define SLOPE 0.01f

// ---------------- fp16 scratch (static device globals) ----------------
__device__ __half g16_style_w[WD * Dd];
__device__ __half g16_sa_qk[Dd * Dd];
__device__ __half g16_sa_kk[Dd * Dd];
__device__ __half g16_sa_vk[Dd * Dd];
__device__ __half g16_sa_ok[Dd * Dd];
__device__ __half g16_ca_kk[Dd * Dd];
__device__ __half g16_ca_ok[Dd * Dd];
__device__ __half g16_ca_qk[TD * Dd];
__device__ __half g16_ca_vk[TD * Dd];
__device__ __half g16_w [Bz * WD];
__device__ __half g16_t [Bz * 64 * TD];

__device__ __half g16_hs[Bz * 65 * Dd];
__device__ __half g16_q [Bz * 65 * Dd];
__device__ __half g16_k [Bz * 65 * Dd];
__device__ __half g16_v [Bz * 65 * Dd];
__device__ __half g16_q2[Bz * 64 * Dd];
__device__ __half g16_v2[Bz * 64 * Dd];
__device__ __half g16_a [Bz * 64 * Dd];
__device__ __half g16_h [Bz * 64 * Dd];

__device__ float g_sc1[Bz * 65 * 65];
__device__ float g_sc2[Bz * 65 * 65];

// ---------------- fp32 -> fp16 convert ----------------
__global__ void cvt16_kernel(const float4* __restrict__ src, __half* __restrict__ dst,
                             int n4)
{
    int i = blockIdx.x * blockDim.x + threadIdx.x;
    if (i >= n4) return;
    float4 v = src[i];
    __half2* d = (__half2*)(dst + (size_t)i * 4);
    d[0] = __floats2half2_rn(v.x, v.y);
    d[1] = __floats2half2_rn(v.z, v.w);
}

// ================= fp16 cp.async GEMM =================
// C[z][M, 4096 (stride cstride)] = A[M,K] @ W[z][K,4096] + bias[z] (+leaky)
// All fp16 (bias fp32). CTA 128x128, BK=64, 512 thr, warp 32x32,
// 4-stage cp.async pipeline; pure ldmatrix + HMMA inner loop.

#define KPA 72
#define KPB 136
#define A_ST (128 * KPA)          // 9216 halves
#define B_ST (64 * KPB)           // 8704 halves
#define STG  (A_ST + B_ST)        // 17920 halves
#define NSTG 4
#define GEMM_SMEM (NSTG * STG * 2)   // 143360 bytes

__device__ __forceinline__ uint32_t smem_u32(const void* p) {
    uint32_t a;
    asm("{ .reg .u64 t; cvta.to.shared.u64 t, %1; cvt.u32.u64 %0, t; }" : "=r"(a) : "l"(p));
    return a;
}
__device__ __forceinline__ void cpa16(uint32_t dst, const void* src) {
    asm volatile("cp.async.ca.shared.global [%0], [%1], 16;" :: "r"(dst), "l"(src)
                 : "memory");
}
__device__ __forceinline__ void ldsm4(uint32_t& r0, uint32_t& r1, uint32_t& r2,
                                      uint32_t& r3, uint32_t addr) {
    asm volatile("ldmatrix.sync.aligned.m8n8.x4.shared.b16 {%0,%1,%2,%3}, [%4];"
                 : "=r"(r0), "=r"(r1), "=r"(r2), "=r"(r3) : "r"(addr));
}
__device__ __forceinline__ void ldsm4t(uint32_t& r0, uint32_t& r1, uint32_t& r2,
                                       uint32_t& r3, uint32_t addr) {
    asm volatile("ldmatrix.sync.aligned.m8n8.x4.trans.shared.b16 {%0,%1,%2,%3}, [%4];"
                 : "=r"(r0), "=r"(r1), "=r"(r2), "=r"(r3) : "r"(addr));
}

__global__ __launch_bounds__(512, 1)
void mma_gemm(const __half* __restrict__ A,
              const __half* __restrict__ W0, const __half* __restrict__ W1,
              const __half* __restrict__ W2,
              const float* __restrict__ b0, const float* __restrict__ b1,
              const float* __restrict__ b2,
              __half* __restrict__ C0, __half* __restrict__ C1, __half* __restrict__ C2,
              int M, int K, int act, int cstride)
{
    const __half* W    = (blockIdx.z == 0) ? W0 : (blockIdx.z == 1) ? W1 : W2;
    const float*  bias = (blockIdx.z == 0) ? b0 : (blockIdx.z == 1) ? b1 : b2;
    __half*       C    = (blockIdx.z == 0) ? C0 : (blockIdx.z == 1) ? C1 : C2;

    extern __shared__ __align__(16) __half smh[];
    const uint32_t smb = smem_u32(smh);
    const int tid  = threadIdx.x;
    const int wid  = tid >> 5;
    const int lane = tid & 31;
    const int bn = blockIdx.x << 7;
    const int bm = blockIdx.y << 7;
    const int wm = (wid >> 2) << 5;
    const int wn = (wid & 3) << 5;
    const int r  = lane >> 2;
    const int c  = lane & 3;

    const int mrem  = M - bm - wm;
    const int mtmax = (mrem >= 32) ? 2 : ((mrem <= 0) ? 0 : 1);

    // A fragment base (non-trans, layout [m][KPA])
    const int t8   = lane >> 3;
    const int row8 = lane & 7;
    const uint32_t a_lm = (uint32_t)((wm + (t8 & 1) * 8 + row8) * KPA * 2 + (t8 >> 1) * 16);
    // B fragment base (trans, layout [k][KPB]): row = (g&1)*8 + row8, col = wn + (g>>1)*8
    const uint32_t b_lm = (uint32_t)(A_ST * 2
                        + ((t8 & 1) * 8 + row8) * KPB * 2
                        + (wn + (t8 >> 1) * 8) * 2);

    float acc[2][4][4];
    #pragma unroll
    for (int i = 0; i < 2; i++)
        #pragma unroll
        for (int j = 0; j < 4; j++)
            #pragma unroll
            for (int t = 0; t < 4; t++) acc[i][j][t] = 0.f;

    const int nkb = K >> 6;   // BK = 64

    // staging: A 1024 chunks (128r x 8), B 1024 chunks (64k x 16) -> 2+2 per thread
    const int a_m  = tid >> 3, a_c8 = tid & 7;          // +64 rows for chunk 1
    const int b_kr = tid >> 4, b_c8 = tid & 15;         // +32 k-rows for chunk 1

    auto load_stage = [&](int kb, int st) {
        const uint32_t base = smb + (uint32_t)st * STG * 2;
        const int kcol = kb << 6;
        #pragma unroll
        for (int i = 0; i < 2; i++) {
            int m  = a_m + i * 64;
            int gm = bm + m;
            if (gm >= M) gm = M - 1;
            cpa16(base + (uint32_t)(m * KPA + a_c8 * 8) * 2,
                  A + (size_t)gm * K + kcol + a_c8 * 8);
        }
        #pragma unroll
        for (int i = 0; i < 2; i++) {
            int kr = b_kr + i * 32;
            cpa16(base + (uint32_t)(A_ST + kr * KPB + b_c8 * 8) * 2,
                  W + (size_t)(kcol + kr) * 4096 + bn + b_c8 * 8);
        }
        asm volatile("cp.async.commit_group;" ::: "memory");
    };

    // prologue: 3 stages in flight
    #pragma unroll
    for (int s = 0; s < 3; s++)
        if (s < nkb) load_stage(s, s);

    for (int kb = 0; kb < nkb; kb++) {
        int pend = nkb - kb - 1;
        if (pend >= 2)      asm volatile("cp.async.wait_group 2;" ::: "memory");
        else if (pend == 1) asm volatile("cp.async.wait_group 1;" ::: "memory");
        else                asm volatile("cp.async.wait_group 0;" ::: "memory");
        __syncthreads();
        if (kb + 3 < nkb) load_stage(kb + 3, (kb + 3) & 3);

        const uint32_t stage = smb + (uint32_t)(kb & 3) * STG * 2;

        #pragma unroll
        for (int ks = 0; ks < 4; ks++) {
            uint32_t af[2][4];
            #pragma unroll
            for (int mt = 0; mt < 2; mt++) {
                if (mt < mtmax)
                    ldsm4(af[mt][0], af[mt][1], af[mt][2], af[mt][3],
                          stage + a_lm + (uint32_t)(mt * 16 * KPA * 2)
                                + (uint32_t)(ks * 32));
            }
            uint32_t bf[4][2];
            #pragma unroll
            for (int p = 0; p < 2; p++) {
                ldsm4t(bf[2 * p][0], bf[2 * p][1], bf[2 * p + 1][0], bf[2 * p + 1][1],
                       stage + b_lm + (uint32_t)(ks * 16 * KPB * 2)
                             + (uint32_t)(p * 32));
            }
            #pragma unroll
            for (int mt = 0; mt < 2; mt++) {
                if (mt < mtmax) {
                    #pragma unroll
                    for (int nt = 0; nt < 4; nt++) {
                        asm volatile(
                            "mma.sync.aligned.m16n8k16.row.col.f32.f16.f16.f32 "
                            "{%0,%1,%2,%3}, {%4,%5,%6,%7}, {%8,%9}, {%0,%1,%2,%3};"
                            : "+f"(acc[mt][nt][0]), "+f"(acc[mt][nt][1]),
                              "+f"(acc[mt][nt][2]), "+f"(acc[mt][nt][3])
                            : "r"(af[mt][0]), "r"(af[mt][1]),
                              "r"(af[mt][2]), "r"(af[mt][3]),
                              "r"(bf[nt][0]), "r"(bf[nt][1]));
                    }
                }
            }
        }
    }

    #pragma unroll
    for (int mt = 0; mt < 2; mt++) {
        if (mt >= mtmax) continue;
        int row0 = bm + wm + mt * 16 + r;
        int row1 = row0 + 8;
        #pragma unroll
        for (int nt = 0; nt < 4; nt++) {
            int col = bn + wn + nt * 8 + c * 2;
            float bb0 = bias[col], bb1 = bias[col + 1];
            if (row0 < M) {
                float v0 = acc[mt][nt][0] + bb0;
                float v1 = acc[mt][nt][1] + bb1;
                if (act) { v0 = v0 >= 0.f ? v0 : SLOPE * v0; v1 = v1 >= 0.f ? v1 : SLOPE * v1; }
                *(__half2*)(C + (size_t)row0 * cstride + col) = __floats2half2_rn(v0, v1);
            }
            if (row1 < M) {
                float v2 = acc[mt][nt][2] + bb0;
                float v3 = acc[mt][nt][3] + bb1;
                if (act) { v2 = v2 >= 0.f ? v2 : SLOPE * v2; v3 = v3 >= 0.f ? v3 : SLOPE * v3; }
                *(__half2*)(C + (size_t)row1 * cstride + col) = __floats2half2_rn(v2, v3);
            }
        }
    }
}

// ================= attention (fp16 in/out, fp32 math) =================

__global__ void zero_sc_kernel(float* sc)
{
    int idx = blockIdx.x * blockDim.x + threadIdx.x;
    if (idx < Bz * 65 * 65) sc[idx] = 0.f;
}

#define SCW 81
#define SC_SMEM (2 * 128 * SCW * 4)

__global__ __launch_bounds__(256)
void attn_scores_part(const __half* __restrict__ Q, const __half* __restrict__ Km,
                      float* __restrict__ SC, int Sq, int Sk, int qbs, int kbs)
{
    extern __shared__ __align__(16) float sq[];
    float* sk = sq + 128 * SCW;
    __shared__ float kn[80];

    const int b  = blockIdx.y;
    const int ch = blockIdx.x;
    const int tid = threadIdx.x;
    const int ty = tid >> 4, tx = tid & 15;

    for (int e = tid; e < Sq * 128; e += 256) {
        int i  = e >> 7;
        int kk = e & 127;
        sq[kk * SCW + i] = __half2float(Q[((size_t)b * qbs + i) * Dd + ch * 128 + kk]);
    }
    for (int e = tid; e < Sk * 128; e += 256) {
        int j  = e >> 7;
        int kk = e & 127;
        sk[kk * SCW + j] = __half2float(Km[((size_t)b * kbs + j) * Dd + ch * 128 + kk]);
    }
    __syncthreads();

    if (tid < Sk) {
        float s = 0.f;
        #pragma unroll 8
        for (int kk = 0; kk < 128; kk++) {
            float v = sk[kk * SCW + tid];
            s += v * v;
        }
        kn[tid] = s;
    }
    __syncthreads();

    float acc[5][5];
    #pragma unroll
    for (int u = 0; u < 5; u++)
        #pragma unroll
        for (int v = 0; v < 5; v++) acc[u][v] = 0.f;

    #pragma unroll 4
    for (int kk = 0; kk < 128; kk++) {
        float a[5], bb[5];
        #pragma unroll
        for (int u = 0; u < 5; u++) a[u]  = sq[kk * SCW + ty * 5 + u];
        #pragma unroll
        for (int v = 0; v < 5; v++) bb[v] = sk[kk * SCW + tx * 5 + v];
        #pragma unroll
        for (int u = 0; u < 5; u++)
            #pragma unroll
            for (int v = 0; v < 5; v++) acc[u][v] += a[u] * bb[v];
    }

    #pragma unroll
    for (int u = 0; u < 5; u++) {
        int i = ty * 5 + u;
        if (i >= Sq) continue;
        #pragma unroll
        for (int v = 0; v < 5; v++) {
            int j = tx * 5 + v;
            if (j >= Sk) continue;
            atomicAdd(&SC[((size_t)b * 65 + i) * 65 + j], 2.f * acc[u][v] - kn[j]);
        }
    }
}

__global__ __launch_bounds__(32)
void softmax_kernel(float* __restrict__ SC, int Sk)
{
    int b = blockIdx.y, i = blockIdx.x;
    float* row = SC + ((size_t)b * 65 + i) * 65;
    int lane = threadIdx.x;

    float v0 = (lane      < Sk) ? row[lane]      : -1e30f;
    float v1 = (lane + 32 < Sk) ? row[lane + 32] : -1e30f;
    float v2 = (lane + 64 < Sk) ? row[lane + 64] : -1e30f;
    float mx = fmaxf(v0, fmaxf(v1, v2));
    #pragma unroll
    for (int o = 16; o; o >>= 1) mx = fmaxf(mx, __shfl_xor_sync(0xffffffff, mx, o));
    float e0 = (lane      < Sk) ? __expf(v0 - mx) : 0.f;
    float e1 = (lane + 32 < Sk) ? __expf(v1 - mx) : 0.f;
    float e2 = (lane + 64 < Sk) ? __expf(v2 - mx) : 0.f;
    float s = e0 + e1 + e2;
    #pragma unroll
    for (int o = 16; o; o >>= 1) s += __shfl_xor_sync(0xffffffff, s, o);
    float inv = 1.f / s;
    if (lane      < Sk) row[lane]      = e0 * inv;
    if (lane + 32 < Sk) row[lane + 32] = e1 * inv;
    if (lane + 64 < Sk) row[lane + 64] = e2 * inv;
}

#define AO_SMEM ((65 * 128 + 65 * 64) * 4)

__global__ __launch_bounds__(256)
void attn_out_chunk(const float* __restrict__ SC, const __half* __restrict__ V,
                    __half* __restrict__ Out, int Sq, int vbs)
{
    extern __shared__ __align__(16) float svs[];
    float* sw = svs + 65 * 128;

    const int b  = blockIdx.y;
    const int ch = blockIdx.x;
    const int tid = threadIdx.x;
    const int tx = tid & 31, ty = tid >> 5;

    for (int e = tid; e < Sq * 128; e += 256) {
        int i  = e >> 7;
        int kk = e & 127;
        svs[e] = __half2float(V[((size_t)b * vbs + i) * Dd + ch * 128 + kk]);
    }
    for (int e = tid; e < Sq * 64; e += 256) {
        int i = e >> 6;
        int j = e & 63;
        sw[e] = SC[((size_t)b * 65 + i) * 65 + j];
    }
    __syncthreads();

    float acc[8][4];
    #pragma unroll
    for (int u = 0; u < 8; u++)
        #pragma unroll
        for (int t = 0; t < 4; t++) acc[u][t] = 0.f;

    for (int i = 0; i < Sq; i++) {
        float4 v4 = *(const float4*)(svs + i * 128 + tx * 4);
        #pragma unroll
        for (int u = 0; u < 8; u++) {
            float w = sw[i * 64 + ty * 8 + u];
            acc[u][0] += w * v4.x;
            acc[u][1] += w * v4.y;
            acc[u][2] += w * v4.z;
            acc[u][3] += w * v4.w;
        }
    }

    #pragma unroll
    for (int u = 0; u < 8; u++) {
        int j = ty * 8 + u;
        __half* o = Out + ((size_t)b * 64 + j) * Dd + ch * 128 + tx * 4;
        *(__half2*)(o)     = __floats2half2_rn(acc[u][0], acc[u][1]);
        *(__half2*)(o + 2) = __floats2half2_rn(acc[u][2], acc[u][3]);
    }
}

// ================= layout kernels =================
__global__ __launch_bounds__(256)
void patchify_kernel(const float* __restrict__ x, __half* __restrict__ hs)
{
    __shared__ float tile[64][65];
    const int y = blockIdx.x;
    const int b = blockIdx.y;
    const int tid = threadIdx.x;
    const int jb = y >> 3, pr = y & 7;

    #pragma unroll
    for (int p = 0; p < 16; p++) {
        int cc = p * 4 + (tid >> 6);
        int xw = tid & 63;
        tile[cc][xw] = x[(((size_t)b * 64 + cc) * 64 + y) * 64 + xw];
    }
    __syncthreads();
    #pragma unroll
    for (int p = 0; p < 16; p++) {
        int xw = p * 4 + (tid >> 6);
        int cc = tid & 63;
        int ib = xw >> 3, pc = xw & 7;
        int n = ib * 8 + jb;
        int d = (pr * 8 + pc) * 64 + cc;
        hs[((size_t)b * 65 + n) * Dd + d] = __float2half(tile[cc][xw]);
    }
}

__global__ __launch_bounds__(256)
void depatchify_kernel(const __half* __restrict__ h, float* __restrict__ out)
{
    __shared__ float tile[64][65];
    const int y = blockIdx.x;
    const int b = blockIdx.y;
    const int tid = threadIdx.x;
    const int jb = y >> 3, pr = y & 7;

    #pragma unroll
    for (int p = 0; p < 16; p++) {
        int xw = p * 4 + (tid >> 6);
        int cc = tid & 63;
        int ib = xw >> 3, pc = xw & 7;
        int n = ib * 8 + jb;
        int d = (pr * 8 + pc) * 64 + cc;
        tile[cc][xw] = __half2float(h[((size_t)b * 64 + n) * Dd + d]);
    }
    __syncthreads();
    #pragma unroll
    for (int p = 0; p < 16; p++) {
        int cc = p * 4 + (tid >> 6);
        int xw = tid & 63;
        out[(((size_t)b * 64 + cc) * 64 + y) * 64 + xw] = tile[cc][xw];
    }
}

// ================= host sequence =================
static void run_cvt(const float* src, __half* dst, size_t n)
{
    int n4 = (int)(n / 4);
    cvt16_kernel<<<(n4 + 255) / 256, 256>>>((const float4*)src, dst, n4);
}

static void run_gemm3(const __half* A,
                      const __half* W0, const __half* W1, const __half* W2,
                      const float* b0, const float* b1, const float* b2,
                      __half* C0, __half* C1, __half* C2,
                      int M, int K, int nz, int act, int cstride)
{
    dim3 grid(32, (M + 127) / 128, nz);
    mma_gemm<<<grid, 512, GEMM_SMEM>>>(A, W0, W1, W2, b0, b1, b2,
                                       C0, C1, C2, M, K, act, cstride);
}

extern "C" void kernel_launch(void* const* d_in, const int* in_sizes, int n_in,
                              void* d_out, int out_size)
{
    const float* x          = (const float*)d_in[0];
    const float* w          = (const float*)d_in[1];
    const float* t_local    = (const float*)d_in[2];
    const float* sa_style_w = (const float*)d_in[3];
    const float* sa_style_b = (const float*)d_in[4];
    const float* sa_kk = (const float*)d_in[5];
    const float* sa_kb = (const float*)d_in[6];
    const float* sa_qk = (const float*)d_in[7];
    const float* sa_qb = (const float*)d_in[8];
    const float* sa_vk = (const float*)d_in[9];
    const float* sa_vb = (const float*)d_in[10];
    const float* sa_ok = (const float*)d_in[11];
    const float* sa_ob = (const float*)d_in[12];
    const float* ca_kk = (const float*)d_in[13];
    const float* ca_kb = (const float*)d_in[14];
    const float* ca_qk = (const float*)d_in[15];
    const float* ca_qb = (const float*)d_in[16];
    const float* ca_vk = (const float*)d_in[17];
    const float* ca_vb = (const float*)d_in[18];
    const float* ca_ok = (const float*)d_in[19];
    const float* ca_ob = (const float*)d_in[20];
    float* out = (float*)d_out;

    __half *sw16, *qk16, *kk16, *vk16, *ok16, *ckk16, *cok16, *cqk16, *cvk16;
    __half *w16, *t16, *hs, *q, *k, *v, *q2, *v2, *a, *h;
    float *sc1, *sc2;
    cudaGetSymbolAddress((void**)&sw16,  g16_style_w);
    cudaGetSymbolAddress((void**)&qk16,  g16_sa_qk);
    cudaGetSymbolAddress((void**)&kk16,  g16_sa_kk);
    cudaGetSymbolAddress((void**)&vk16,  g16_sa_vk);
    cudaGetSymbolAddress((void**)&ok16,  g16_sa_ok);
    cudaGetSymbolAddress((void**)&ckk16, g16_ca_kk);
    cudaGetSymbolAddress((void**)&cok16, g16_ca_ok);
    cudaGetSymbolAddress((void**)&cqk16, g16_ca_qk);
    cudaGetSymbolAddress((void**)&cvk16, g16_ca_vk);
    cudaGetSymbolAddress((void**)&w16,   g16_w);
    cudaGetSymbolAddress((void**)&t16,   g16_t);
    cudaGetSymbolAddress((void**)&hs,    g16_hs);
    cudaGetSymbolAddress((void**)&q,     g16_q);
    cudaGetSymbolAddress((void**)&k,     g16_k);
    cudaGetSymbolAddress((void**)&v,     g16_v);
    cudaGetSymbolAddress((void**)&q2,    g16_q2);
    cudaGetSymbolAddress((void**)&v2,    g16_v2);
    cudaGetSymbolAddress((void**)&a,     g16_a);
    cudaGetSymbolAddress((void**)&h,     g16_h);
    cudaGetSymbolAddress((void**)&sc1,   g_sc1);
    cudaGetSymbolAddress((void**)&sc2,   g_sc2);

    cudaFuncSetAttribute(mma_gemm, cudaFuncAttributeMaxDynamicSharedMemorySize, GEMM_SMEM);
    cudaFuncSetAttribute(attn_scores_part, cudaFuncAttributeMaxDynamicSharedMemorySize, SC_SMEM);
    cudaFuncSetAttribute(attn_out_chunk, cudaFuncAttributeMaxDynamicSharedMemorySize, AO_SMEM);

    // ---- weight/input conversion (fp32 -> fp16, streaming) ----
    run_cvt(w,          w16,   (size_t)Bz * WD);
    run_cvt(t_local,    t16,   (size_t)Bz * 64 * TD);
    run_cvt(sa_style_w, sw16,  (size_t)WD * Dd);
    run_cvt(ca_qk,      cqk16, (size_t)TD * Dd);
    run_cvt(ca_vk,      cvk16, (size_t)TD * Dd);
    run_cvt(sa_qk,      qk16,  (size_t)Dd * Dd);
    run_cvt(sa_kk,      kk16,  (size_t)Dd * Dd);
    run_cvt(sa_vk,      vk16,  (size_t)Dd * Dd);
    run_cvt(sa_ok,      ok16,  (size_t)Dd * Dd);
    run_cvt(ca_kk,      ckk16, (size_t)Dd * Dd);
    run_cvt(ca_ok,      cok16, (size_t)Dd * Dd);

    zero_sc_kernel<<<(Bz * 65 * 65 + 255) / 256, 256>>>(sc1);
    zero_sc_kernel<<<(Bz * 65 * 65 + 255) / 256, 256>>>(sc2);
    patchify_kernel<<<dim3(64, Bz), 256>>>(x, hs);

    // style token -> hs row 64 (stride 65*Dd)
    run_gemm3(w16, sw16, sw16, sw16, sa_style_b, sa_style_b, sa_style_b,
              hs + 64 * Dd, hs + 64 * Dd, hs + 64 * Dd, Bz, WD, 1, 0, 65 * Dd);
    // CA q/v from t_local (z=2)
    run_gemm3(t16, cqk16, cvk16, cvk16, ca_qb, ca_vb, ca_vb,
              q2, v2, v2, Bz * 64, TD, 2, 0, Dd);

    // SA q/k/v fused (M=520, K=4096, z=3)
    run_gemm3(hs, qk16, kk16, vk16, sa_qb, sa_kb, sa_vb,
              q, k, v, Bz * 65, Dd, 3, 0, Dd);

    // SA L2 attention
    attn_scores_part<<<dim3(32, Bz), 256, SC_SMEM>>>(q, k, sc1, 65, 65, 65, 65);
    softmax_kernel<<<dim3(65, Bz), 32>>>(sc1, 65);
    attn_out_chunk<<<dim3(32, Bz), 256, AO_SMEM>>>(sc1, v, a, 65, 65);

    // SA output projection + leaky relu
    run_gemm3(a, ok16, ok16, ok16, sa_ob, sa_ob, sa_ob,
              h, h, h, Bz * 64, Dd, 1, 1, Dd);

    // CA key projection
    run_gemm3(h, ckk16, ckk16, ckk16, ca_kb, ca_kb, ca_kb,
              k, k, k, Bz * 64, Dd, 1, 0, Dd);

    // CA L2 attention
    attn_scores_part<<<dim3(32, Bz), 256, SC_SMEM>>>(q2, k, sc2, 64, 64, 64, 64);
    softmax_kernel<<<dim3(64, Bz), 32>>>(sc2, 64);
    attn_out_chunk<<<dim3(32, Bz), 256, AO_SMEM>>>(sc2, v2, a, 64, 64);

    // CA output projection + leaky relu
    run_gemm3(a, cok16, cok16, cok16, ca_ob, ca_ob, ca_ob,
              h, h, h, Bz * 64, Dd, 1, 1, Dd);

    depatchify_kernel<<<dim3(64, Bz), 256>>>(h, out);
}